// round 6
// baseline (speedup 1.0000x reference)
#include <cuda_runtime.h>
#include <cuda_bf16.h>

#define BINS 10
#define TPB 256
#define WARPS (TPB / 32)
#define BLKS_PER_SM 8
#define NBLOCKS (148 * BLKS_PER_SM)   // exactly one wave at occupancy 8

#define BIAS 4096.0f                  // count-packing bias; Sum(bce) per slot << BIAS

// Global scratch (no allocations allowed): per-bin accumulators + completion ticket.
// Self-resetting so every graph replay starts from identical state.
__device__ double g_sum[BINS];
__device__ double g_cnt[BINS];
__device__ unsigned int g_ticket;

// sigmoid(x) = 0.5 + 0.5*tanh(x/2): FMUL + MUFU.TANH + FMA
__device__ __forceinline__ float sigmoid_fast(float x) {
    float h = 0.5f * x;
    float th;
    asm("tanh.approx.f32 %0, %1;" : "=f"(th) : "f"(h));
    return fmaf(0.5f, th, 0.5f);
}

// One element. Slot s[warp][bin][lane] (float): bank = lane -> conflict-free.
// acc += BIAS + bce  packs {count, bce_sum} into one float.
__device__ __forceinline__ void proc(float pk, int tk, float* __restrict__ base) {
    float z  = sigmoid_fast(pk);
    float tf = (float)tk;
    float g  = fabsf(z - tf);
    int idx  = min(__float2int_rz(g * 10.0f), BINS - 1);

    // softplus(z) for z in (0,1), bias folded into the constant term:
    // ln(1+e^z) = ln2 + z/2 + z^2/8 - z^4/192 + z^6/2880 - 17 z^8/645120
    float u = z * z;
    float p = fmaf(-2.6351690e-5f, u, 3.4722222e-4f);
    p = fmaf(p, u, -5.2083335e-3f);
    p = fmaf(p, u, 0.125f);
    float sp = fmaf(0.5f, z, 0.69314718f + BIAS) + p * u;
    float v  = fmaf(-tf, z, sp);          // BIAS + bce

    float* s = base + idx * 32;
    *s += v;
}

__global__ void __launch_bounds__(TPB, BLKS_PER_SM)
ghmc_fused_kernel(const float* __restrict__ pred,
                  const int* __restrict__ target,
                  float* __restrict__ out,
                  int n) {
    __shared__ float s_acc[WARPS][BINS][32];   // 10,240 B
    __shared__ float s_bs[BINS], s_bc[BINS];

    const int tid  = threadIdx.x;
    const int lane = tid & 31;
    const int warp = tid >> 5;

    // Zero shared accumulators.
    {
        float* a = &s_acc[0][0][0];
        #pragma unroll
        for (int i = 0; i < WARPS * BINS * 32 / TPB; ++i) a[tid + i * TPB] = 0.0f;
    }
    __syncthreads();

    float* base = &s_acc[warp][0][lane];

    const int stride = gridDim.x * TPB;
    const int gtid   = blockIdx.x * TPB + tid;

    // Vectorized loop with software prefetch: next float4/int4 loads issue
    // before processing the current ones (2x LDG.128 pairs in flight).
    const int nv = n >> 2;
    const float4* p4 = (const float4*)pred;
    const int4*   t4 = (const int4*)target;

    int i = gtid;
    if (i < nv) {
        float4 pa = p4[i];
        int4   ta = t4[i];
        for (;;) {
            int j = i + stride;
            bool has = (j < nv);
            float4 pn; int4 tn;
            if (has) { pn = p4[j]; tn = t4[j]; }
            proc(pa.x, ta.x, base);
            proc(pa.y, ta.y, base);
            proc(pa.z, ta.z, base);
            proc(pa.w, ta.w, base);
            if (!has) break;
            pa = pn; ta = tn; i = j;
        }
    }
    // Scalar tail (empty for this shape; defensive).
    for (int j = (nv << 2) + gtid; j < n; j += stride)
        proc(pred[j], target[j], base);

    __syncthreads();

    // Block reduction: warp w handles bins w, w+WARPS, ...
    // Unpack {count, sum} per slot BEFORE summing (keeps magnitudes small/exact).
    for (int b = warp; b < BINS; b += WARPS) {
        float vs = 0.0f, vc = 0.0f;
        #pragma unroll
        for (int w = 0; w < WARPS; ++w) {
            float acc = s_acc[w][b][lane];
            float c   = floorf(acc * (1.0f / BIAS));
            float s   = fmaf(-c, BIAS, acc);
            vs += s;
            vc += c;
        }
        #pragma unroll
        for (int o = 16; o > 0; o >>= 1) {
            vs += __shfl_xor_sync(0xFFFFFFFFu, vs, o);
            vc += __shfl_xor_sync(0xFFFFFFFFu, vc, o);
        }
        if (lane == 0) { s_bs[b] = vs; s_bc[b] = vc; }
    }
    __syncthreads();

    // Thread 0 only: global atomics -> fence -> ticket.
    if (tid == 0) {
        #pragma unroll
        for (int b = 0; b < BINS; ++b) {
            atomicAdd(&g_sum[b], (double)s_bs[b]);
            atomicAdd(&g_cnt[b], (double)s_bc[b]);
        }
        __threadfence();
        unsigned t = atomicAdd(&g_ticket, 1u);
        if (t == gridDim.x - 1) {
            __threadfence();
            // loss = ( sum_{b: cnt>0} S_b / cnt_b ) / n_nonempty   (tot cancels)
            double acc = 0.0, nn = 0.0;
            #pragma unroll
            for (int b = 0; b < BINS; ++b) {
                double c = atomicAdd(&g_cnt[b], 0.0);   // L2-coherent read
                double s = atomicAdd(&g_sum[b], 0.0);
                if (c > 0.0) { nn += 1.0; acc += s / c; }
            }
            if (nn < 1.0) nn = 1.0;
            out[0] = (float)(acc / nn);
            // Reset state for the next graph replay.
            #pragma unroll
            for (int b = 0; b < BINS; ++b) { g_sum[b] = 0.0; g_cnt[b] = 0.0; }
            g_ticket = 0u;
        }
    }
}

extern "C" void kernel_launch(void* const* d_in, const int* in_sizes, int n_in,
                              void* d_out, int out_size) {
    const float* pred   = (const float*)d_in[0];
    const int*   target = (const int*)d_in[1];
    float*       out    = (float*)d_out;
    int n = in_sizes[0];

    ghmc_fused_kernel<<<NBLOCKS, TPB>>>(pred, target, out, n);
}

// round 7
// speedup vs baseline: 1.0721x; 1.0721x over previous
#include <cuda_runtime.h>
#include <cuda_bf16.h>

#define BINS 10
#define TPB 256
#define WARPS (TPB / 32)
#define BLKS_PER_SM 4
#define NBLOCKS (148 * BLKS_PER_SM)   // 592: one wave at occupancy 4
#define SETS 2

// Global scratch (no allocations allowed): per-bin accumulators + completion ticket.
// Self-resetting so every graph replay starts from identical state.
__device__ double g_sum[BINS];
__device__ double g_cnt[BINS];
__device__ unsigned int g_ticket;

// sigmoid(x) = 0.5 + 0.5*tanh(x/2): FMUL + MUFU.TANH + FMA
__device__ __forceinline__ float sigmoid_fast(float x) {
    float h = 0.5f * x;
    float th;
    asm("tanh.approx.f32 %0, %1;" : "=f"(th) : "f"(h));
    return fmaf(0.5f, th, 0.5f);
}

// One element. Slot layout s[set][warp][bin][lane] (float2): bank = f(lane) -> conflict-free.
__device__ __forceinline__ void proc(float pk, int tk, float2* __restrict__ base) {
    float z  = sigmoid_fast(pk);
    float tf = (float)tk;
    float g  = fabsf(z - tf);
    int idx  = min(__float2int_rz(g * 10.0f), BINS - 1);

    // softplus(z), z in (0,1):
    // ln(1+e^z) = ln2 + z/2 + z^2/8 - z^4/192 + z^6/2880 - 17 z^8/645120
    float u = z * z;
    float p = fmaf(-2.6351690e-5f, u, 3.4722222e-4f);
    p = fmaf(p, u, -5.2083335e-3f);
    p = fmaf(p, u, 0.125f);
    float sp  = fmaf(0.5f, z, 0.69314718f) + p * u;
    float bce = fmaf(-tf, z, sp);

    float2* s = base + idx * 32;
    float2 v = *s;
    v.x += bce;
    v.y += 1.0f;
    *s = v;
}

__global__ void __launch_bounds__(TPB, BLKS_PER_SM)
ghmc_fused_kernel(const float* __restrict__ pred,
                  const int* __restrict__ target,
                  float* __restrict__ out,
                  int n) {
    __shared__ float2 s_acc[SETS][WARPS][BINS][32];   // 40,960 B
    __shared__ float s_bs[BINS], s_bc[BINS];

    const int tid  = threadIdx.x;
    const int lane = tid & 31;
    const int warp = tid >> 5;

    // Zero shared accumulators.
    {
        float2* a = &s_acc[0][0][0][0];
        #pragma unroll
        for (int i = 0; i < SETS * WARPS * BINS * 32 / TPB; ++i)
            a[tid + i * TPB] = make_float2(0.0f, 0.0f);
    }
    __syncthreads();

    float2* base0 = &s_acc[0][warp][0][lane];
    float2* base1 = &s_acc[1][warp][0][lane];

    const int stride = gridDim.x * TPB;          // 151,552
    const int gtid   = blockIdx.x * TPB + tid;

    const int nv = n >> 2;                       // float4 count
    const float4* p4 = (const float4*)pred;
    const int4*   t4 = (const int4*)target;

    // ---- Uniform counted main loop: unroll 4, loads front-batched (MLP=8) ----
    const int K = nv / (4 * stride);             // identical for every thread
    int i = gtid;
    for (int it = 0; it < K; ++it) {
        float4 pa = __ldcs(p4 + i);
        float4 pb = __ldcs(p4 + i + stride);
        float4 pc = __ldcs(p4 + i + 2 * stride);
        float4 pd = __ldcs(p4 + i + 3 * stride);
        int4   ta = __ldcs(t4 + i);
        int4   tb = __ldcs(t4 + i + stride);
        int4   tc = __ldcs(t4 + i + 2 * stride);
        int4   td = __ldcs(t4 + i + 3 * stride);
        i += 4 * stride;

        proc(pa.x, ta.x, base0); proc(pa.y, ta.y, base0);
        proc(pa.z, ta.z, base0); proc(pa.w, ta.w, base0);
        proc(pb.x, tb.x, base1); proc(pb.y, tb.y, base1);
        proc(pb.z, tb.z, base1); proc(pb.w, tb.w, base1);
        proc(pc.x, tc.x, base0); proc(pc.y, tc.y, base0);
        proc(pc.z, tc.z, base0); proc(pc.w, tc.w, base0);
        proc(pd.x, td.x, base1); proc(pd.y, td.y, base1);
        proc(pd.z, td.z, base1); proc(pd.w, td.w, base1);
    }
    // ---- Remainder float4s (grid-stride, alternating sets) ----
    int setsel = 0;
    for (; i < nv; i += stride) {
        float4 pa = __ldcs(p4 + i);
        int4   ta = __ldcs(t4 + i);
        float2* b = setsel ? base1 : base0;
        setsel ^= 1;
        proc(pa.x, ta.x, b); proc(pa.y, ta.y, b);
        proc(pa.z, ta.z, b); proc(pa.w, ta.w, b);
    }
    // ---- Scalar tail (empty for this shape; defensive) ----
    for (int j = (nv << 2) + gtid; j < n; j += stride)
        proc(pred[j], target[j], base0);

    __syncthreads();

    // Block reduction: warp w handles bins w, w+WARPS, ...
    for (int b = warp; b < BINS; b += WARPS) {
        float vs = 0.0f, vc = 0.0f;
        #pragma unroll
        for (int s = 0; s < SETS; ++s) {
            #pragma unroll
            for (int w = 0; w < WARPS; ++w) {
                float2 v = s_acc[s][w][b][lane];
                vs += v.x;
                vc += v.y;
            }
        }
        #pragma unroll
        for (int o = 16; o > 0; o >>= 1) {
            vs += __shfl_xor_sync(0xFFFFFFFFu, vs, o);
            vc += __shfl_xor_sync(0xFFFFFFFFu, vc, o);
        }
        if (lane == 0) { s_bs[b] = vs; s_bc[b] = vc; }
    }
    __syncthreads();

    // Thread 0 only: global atomics -> fence -> ticket; last block finalizes.
    if (tid == 0) {
        #pragma unroll
        for (int b = 0; b < BINS; ++b) {
            atomicAdd(&g_sum[b], (double)s_bs[b]);
            atomicAdd(&g_cnt[b], (double)s_bc[b]);
        }
        __threadfence();
        unsigned t = atomicAdd(&g_ticket, 1u);
        if (t == gridDim.x - 1) {
            __threadfence();
            // loss = ( sum_{b: cnt>0} S_b / cnt_b ) / n_nonempty   (tot cancels)
            double acc = 0.0, nn = 0.0;
            #pragma unroll
            for (int b = 0; b < BINS; ++b) {
                double c = atomicAdd(&g_cnt[b], 0.0);   // L2-coherent read
                double s = atomicAdd(&g_sum[b], 0.0);
                if (c > 0.0) { nn += 1.0; acc += s / c; }
            }
            if (nn < 1.0) nn = 1.0;
            out[0] = (float)(acc / nn);
            // Reset state for the next graph replay.
            #pragma unroll
            for (int b = 0; b < BINS; ++b) { g_sum[b] = 0.0; g_cnt[b] = 0.0; }
            g_ticket = 0u;
        }
    }
}

extern "C" void kernel_launch(void* const* d_in, const int* in_sizes, int n_in,
                              void* d_out, int out_size) {
    const float* pred   = (const float*)d_in[0];
    const int*   target = (const int*)d_in[1];
    float*       out    = (float*)d_out;
    int n = in_sizes[0];

    ghmc_fused_kernel<<<NBLOCKS, TPB>>>(pred, target, out, n);
}